// round 16
// baseline (speedup 1.0000x reference)
#include <cuda_runtime.h>
#include <cuda_fp16.h>
#include <cstdint>

#define CDIM 256
#define KCB  512

static const int N_ENC0  = 8*256*64*64;        // 8388608
static const int OFF_Z   = N_ENC0;
static const int OFF_STE = N_ENC0 + 8*2*64*64; // + 65536

// ---- scratch (device globals; no allocation anywhere) ----
__device__ float g_cbsq[2*KCB];         // ||cb||^2, 1024 rows
// fp16 hi/lo split operands, k-PERMUTED within each 16-chunk:
// j=k&15 -> slot = ((j&7)>>1)*4 + ((j>>3)<<1) + (j&1)   (lane t4 owns slots 4t4..4t4+3)
__device__ __half g_ehi[43008*256];     // concat enc0|enc1|enc2 rows
__device__ __half g_elo[43008*256];
__device__ __half g_cbhi[1024*256];     // cb0 rows 0..511, cb1 rows 512..1023
__device__ __half g_cblo[1024*256];
// per-(quarter, position) partials: cb0: q*43008 + pos ; cb1: 172032 + q*32768 + pos
__device__ float g_hM[303104];
__device__ float g_hL[303104];          // only cb0 slots used
__device__ int   g_hI[303104];

// m16n8k16 fp16 MMA, fp32 accum (sm_80+ PTX)
__device__ __forceinline__ void mma_f16(float* c, uint2 a01, uint2 a23, uint2 b) {
    asm volatile("mma.sync.aligned.m16n8k16.row.col.f32.f16.f16.f32 "
        "{%0,%1,%2,%3}, {%4,%5,%6,%7}, {%8,%9}, {%0,%1,%2,%3};"
        : "+f"(c[0]), "+f"(c[1]), "+f"(c[2]), "+f"(c[3])
        : "r"(a01.x), "r"(a23.x), "r"(a01.y), "r"(a23.y),
          "r"(b.x),  "r"(b.y));
}

__device__ __forceinline__ float ex2a(float x) {
    float r; asm("ex2.approx.f32 %0, %1;" : "=f"(r) : "f"(x)); return r;
}
#define LOG2E 1.4426950408889634f

__device__ __forceinline__ int permcol(int k) {
    int j = k & 15;
    return (k & ~15) + ((j & 7) >> 1)*4 + ((j >> 3) << 1) + (j & 1);
}

// ======================= prep kernels =======================
// codebook: squared norms + fp16 hi/lo split (k-permuted). grid 1024, block 256.
__global__ void __launch_bounds__(256) cbprep_kernel(const float* __restrict__ cbs)
{
    __shared__ float red[8];
    int r = blockIdx.x, k = threadIdx.x;
    float v = cbs[(size_t)r*256 + k];
    __half h = __float2half_rn(v);
    __half l = __float2half_rn(v - __half2float(h));
    size_t o = (size_t)r*256 + permcol(k);
    g_cbhi[o] = h; g_cblo[o] = l;
    float s = v*v;
    #pragma unroll
    for (int off = 16; off > 0; off >>= 1) s += __shfl_xor_sync(0xffffffffu, s, off);
    if ((k & 31) == 0) red[k >> 5] = s;
    __syncthreads();
    if (k == 0) {
        float t = 0.f;
        #pragma unroll
        for (int i = 0; i < 8; i++) t += red[i];
        g_cbsq[r] = t;
    }
}

// stride-4 4x4 conv, 3 in-ch -> 256 out-ch; downsample fused for scales 1/2;
// writes fp16 split (+ NCHW fp32 output region 0 for scale0 via smem transpose).
// which==0: grid (128,8)  y=bx>>1, x-half = bx&1
// which==1: grid (32,8)   (inline f=2 avg)    which==2: grid (16,8) (inline f=4 avg)
__global__ void __launch_bounds__(256) conv_kernel(
    const float* __restrict__ image, const float* __restrict__ w,
    const float* __restrict__ bias, float* __restrict__ out, int which)
{
    __shared__ __align__(16) float ins[12][256];
    __shared__ float stage[256][17];
    int o = threadIdx.x;
    int b = blockIdx.y;

    int y, xh = 0;
    if (which == 0) { y = blockIdx.x >> 1; xh = blockIdx.x & 1; }
    else            { y = blockIdx.x; }

    if (which == 0) {
        // fill only the used half: cols [128*xh, 128*xh+128)
        for (int i = o; i < 12*128; i += 256) {
            int x = (i & 127) + 128*xh; int r = i >> 7;
            ins[r][x] = image[(((size_t)b*3 + (r>>2))*256 + 4*y + (r&3))*256 + x];
        }
    } else if (which == 1) {
        // img1[row=4y+ky][x] = 0.25*(p(2row,2x)+p(2row,2x+1)+p(2row+1,2x)+p(2row+1,2x+1))
        for (int i = o; i < 12*128; i += 256) {
            int x = i & 127; int r = i >> 7;
            int ry = 2*(4*y + (r & 3));
            const float* p = image + ((size_t)b*3 + (r>>2))*65536 + ry*256 + 2*x;
            ins[r][x] = 0.25f*(p[0] + p[1] + p[256] + p[257]);
        }
    } else {
        for (int i = o; i < 12*64; i += 256) {
            int x = i & 63; int r = i >> 6;
            int ry = 4*(4*y + (r & 3)) + 1;
            const float* p = image + ((size_t)b*3 + (r>>2))*65536 + ry*256 + 4*x + 1;
            ins[r][x] = 0.25f*(p[0] + p[1] + p[256] + p[257]);
        }
    }

    float wreg[48];
    #pragma unroll
    for (int j = 0; j < 48; j++) wreg[j] = w[(size_t)o*48 + j];
    float bo = bias[o];
    __syncthreads();

    int rowbase = (which == 0) ? (b*64 + y)*64
                : (which == 1) ? 32768 + (b*32 + y)*32
                               : 40960 + (b*16 + y)*16;
    int oc = permcol(o);

    if (which == 0) {
        for (int xc = 32*xh; xc < 32*xh + 32; xc += 16) {
            for (int x2 = 0; x2 < 16; x2 += 2) {
                int x = xc + x2;
                float aA = bo, aB = bo;
                #pragma unroll
                for (int r = 0; r < 12; r++) {
                    float4 vA = *(const float4*)&ins[r][4*x];
                    float4 vB = *(const float4*)&ins[r][4*x + 4];
                    aA += wreg[r*4+0]*vA.x; aB += wreg[r*4+0]*vB.x;
                    aA += wreg[r*4+1]*vA.y; aB += wreg[r*4+1]*vB.y;
                    aA += wreg[r*4+2]*vA.z; aB += wreg[r*4+2]*vB.z;
                    aA += wreg[r*4+3]*vA.w; aB += wreg[r*4+3]*vB.w;
                }
                size_t pA = (size_t)rowbase + x, pB = pA + 1;
                __half hA = __float2half_rn(aA);
                __half lA = __float2half_rn(aA - __half2float(hA));
                __half hB = __float2half_rn(aB);
                __half lB = __float2half_rn(aB - __half2float(hB));
                g_ehi[pA*256 + oc] = hA; g_elo[pA*256 + oc] = lA;
                g_ehi[pB*256 + oc] = hB; g_elo[pB*256 + oc] = lB;
                stage[o][x2] = aA; stage[o][x2+1] = aB;
            }
            __syncthreads();
            int xx = o & 15, cg = o >> 4;
            #pragma unroll
            for (int c0 = 0; c0 < 16; c0++) {
                int c = c0*16 + cg;
                out[((size_t)(b*256 + c)*64 + y)*64 + xc + xx] = stage[c][xx];
            }
            __syncthreads();
        }
    } else {
        int Hout = (which == 1) ? 32 : 16;
        for (int x = 0; x < Hout; x += 2) {
            float aA = bo, aB = bo;
            #pragma unroll
            for (int r = 0; r < 12; r++) {
                float4 vA = *(const float4*)&ins[r][4*x];
                float4 vB = *(const float4*)&ins[r][4*x + 4];
                aA += wreg[r*4+0]*vA.x; aB += wreg[r*4+0]*vB.x;
                aA += wreg[r*4+1]*vA.y; aB += wreg[r*4+1]*vB.y;
                aA += wreg[r*4+2]*vA.z; aB += wreg[r*4+2]*vB.z;
                aA += wreg[r*4+3]*vA.w; aB += wreg[r*4+3]*vB.w;
            }
            size_t pA = (size_t)rowbase + x, pB = pA + 1;
            __half hA = __float2half_rn(aA);
            __half lA = __float2half_rn(aA - __half2float(hA));
            __half hB = __float2half_rn(aB);
            __half lB = __float2half_rn(aB - __half2float(hB));
            g_ehi[pA*256 + oc] = hA; g_elo[pA*256 + oc] = lA;
            g_ehi[pB*256 + oc] = hB; g_elo[pB*256 + oc] = lB;
        }
    }
}

// ======================= fp16 mma.sync distance =======================
// CTA: M=128 positions x N=128 codes (quarter codebook), K=256 in 8 chunks of 32.
// dot ~= Ahi*Bhi + Ahi*Blo + Alo*Bhi (products exact in fp32 accum; dropped lo*lo ~2^-22).
// 8 warps: wm=w&1 (M 64), wn=w>>1 (N 32). Warp tile 64x32, 3 x m16n8k16 per (mt,u).
// Epilogue: two-pass (max/argmax, then sum ex2). cb1 (seg==1) skips L entirely.
#define STRH 48
#define TILEH (128*STRH)
#define DSMEM (4*TILEH*2 + 512)        // 49664 bytes -> 2 CTAs/SM

__global__ void __launch_bounds__(256, 2) dist_mma_kernel()
{
    extern __shared__ char smem[];
    __half* sAhi = (__half*)smem;
    __half* sAlo = sAhi + TILEH;
    __half* sBhi = sAlo + TILEH;
    __half* sBlo = sBhi + TILEH;
    float*  cbs_s = (float*)(smem + 4*TILEH*2);

    int tid = threadIdx.x;
    int lane = tid & 31, w = tid >> 5;
    int g = lane >> 2, t4 = lane & 3;
    int wm = w & 1, wn = w >> 1;

    int blk = blockIdx.x;
    int seg, mtile, q;
    if (blk < 1344) { seg = 0; mtile = blk >> 2; q = blk & 3; }
    else            { seg = 1; mtile = (blk - 1344) >> 2; q = (blk - 1344) & 3; }

    const __half* Ahi_g = g_ehi + (size_t)mtile*128*256;
    const __half* Alo_g = g_elo + (size_t)mtile*128*256;
    int cbrow = (seg ? 512 : 0) + q*128;
    const __half* Bhi_g = g_cbhi + (size_t)cbrow*256;
    const __half* Blo_g = g_cblo + (size_t)cbrow*256;

    if (tid < 128) cbs_s[tid] = g_cbsq[cbrow + tid];

    float acc[4][4][4];
    #pragma unroll
    for (int mt = 0; mt < 4; mt++)
        #pragma unroll
        for (int u = 0; u < 4; u++)
            #pragma unroll
            for (int e = 0; e < 4; e++) acc[mt][u][e] = 0.f;

    const __half* gsrc[4] = {Ahi_g, Alo_g, Bhi_g, Blo_g};
    __half* sdst[4] = {sAhi, sAlo, sBhi, sBlo};

    for (int kc = 0; kc < 8; kc++) {
        if (kc > 0) __syncthreads();
        #pragma unroll
        for (int op = 0; op < 4; op++) {
            #pragma unroll
            for (int it = 0; it < 2; it++) {
                int c = it*256 + tid;
                int r = c >> 2, sgs = c & 3;
                *(uint4*)(sdst[op] + r*STRH + sgs*8) =
                    *(const uint4*)(gsrc[op] + (size_t)r*256 + kc*32 + sgs*8);
            }
        }
        __syncthreads();

        #pragma unroll
        for (int s = 0; s < 2; s++) {
            int ko = s*16 + t4*4;
            uint2 bhf[4], blf[4];
            #pragma unroll
            for (int u = 0; u < 4; u++) {
                int br = (wn*32 + u*8 + g)*STRH + ko;
                bhf[u] = *(uint2*)(sBhi + br);
                blf[u] = *(uint2*)(sBlo + br);
            }
            #pragma unroll
            for (int mt = 0; mt < 4; mt++) {
                int ar = (wm*64 + mt*16 + g)*STRH + ko;
                uint2 ah0 = *(uint2*)(sAhi + ar);
                uint2 ah1 = *(uint2*)(sAhi + ar + 8*STRH);
                uint2 al0 = *(uint2*)(sAlo + ar);
                uint2 al1 = *(uint2*)(sAlo + ar + 8*STRH);
                #pragma unroll
                for (int u = 0; u < 4; u++) {
                    mma_f16(acc[mt][u], ah0, ah1, bhf[u]);
                    mma_f16(acc[mt][u], ah0, ah1, blf[u]);
                    mma_f16(acc[mt][u], al0, al1, bhf[u]);
                }
            }
        }
    }
    __syncthreads();

    float* Mp = (float*)smem;           // [128][4]
    float* Lp = Mp + 512;
    int*   Ip = (int*)(Mp + 1024);

    const float NEG = -3.402823466e38f;
    #pragma unroll
    for (int mt = 0; mt < 4; mt++) {
        #pragma unroll
        for (int half = 0; half < 2; half++) {
            int row = wm*64 + mt*16 + g + half*8;
            float sv[8];
            #pragma unroll
            for (int u = 0; u < 4; u++)
                #pragma unroll
                for (int j = 0; j < 2; j++) {
                    int col = wn*32 + u*8 + 2*t4 + j;
                    sv[u*2 + j] = 2.f*acc[mt][u][half*2 + j] - cbs_s[col];
                }
            float M = NEG; int I = 0;
            #pragma unroll
            for (int t = 0; t < 8; t++) {
                int col = wn*32 + (t >> 1)*8 + 2*t4 + (t & 1);
                if (sv[t] > M) { M = sv[t]; I = col; }
            }
            #pragma unroll
            for (int off = 1; off <= 2; off <<= 1) {
                float m2 = __shfl_xor_sync(0xffffffffu, M, off);
                int   i2 = __shfl_xor_sync(0xffffffffu, I, off);
                if (m2 > M || (m2 == M && i2 < I)) I = i2;
                M = fmaxf(M, m2);
            }
            float L = 0.f;
            if (seg == 0) {
                float ls = 0.f;
                #pragma unroll
                for (int t = 0; t < 8; t++) ls += ex2a((sv[t] - M)*LOG2E);
                #pragma unroll
                for (int off = 1; off <= 2; off <<= 1)
                    ls += __shfl_xor_sync(0xffffffffu, ls, off);
                L = ls;
            }
            if (t4 == 0) { Mp[row*4 + wn] = M; Lp[row*4 + wn] = L; Ip[row*4 + wn] = I; }
        }
    }
    __syncthreads();

    if (tid < 128) {
        float M = Mp[tid*4], L = Lp[tid*4]; int I = Ip[tid*4];
        #pragma unroll
        for (int n = 1; n < 4; n++) {
            float m2 = Mp[tid*4 + n];
            float mn = fmaxf(M, m2);
            L = L*ex2a((M - mn)*LOG2E) + Lp[tid*4 + n]*ex2a((m2 - mn)*LOG2E);
            if (m2 > M) I = Ip[tid*4 + n];
            M = mn;
        }
        int pos = mtile*128 + tid;
        int slot = seg ? (172032 + q*32768 + pos) : (q*43008 + pos);
        g_hM[slot] = M; g_hI[slot] = q*128 + I;
        if (seg == 0) g_hL[slot] = L;
    }
}

// ======================= fuse =======================
__device__ __forceinline__ void merge4(int pos, int base, int stride, float& P, int& idx)
{
    float M = g_hM[base + pos], L = g_hL[base + pos]; int I = g_hI[base + pos];
    #pragma unroll
    for (int n = 1; n < 4; n++) {
        int s = base + n*stride + pos;
        float m2 = g_hM[s], l2 = g_hL[s];
        float mn = fmaxf(M, m2);
        L = L*ex2a((M - mn)*LOG2E) + l2*ex2a((m2 - mn)*LOG2E);
        if (m2 > M) I = g_hI[s];
        M = mn;
    }
    P = 1.f / L; idx = I;
}

__device__ __forceinline__ int merge4max(int pos, int base, int stride)
{
    float M = g_hM[base + pos]; int I = g_hI[base + pos];
    #pragma unroll
    for (int n = 1; n < 4; n++) {
        int s = base + n*stride + pos;
        float m2 = g_hM[s];
        if (m2 > M) { M = m2; I = g_hI[s]; }
    }
    return I;
}

// grid (16, 8, 4): blockIdx.z selects a 64-channel slice; z-writes on slice 0 only.
__global__ void __launch_bounds__(256) fuse_kernel(
    const float* __restrict__ cbs, float* __restrict__ out)
{
    const float* cb0 = cbs;
    const float* cb1 = cbs + (size_t)KCB*CDIM;
    int x = threadIdx.x & 63;
    int y = blockIdx.x*4 + (threadIdx.x >> 6);
    int b = blockIdx.y;
    int cz = blockIdx.z;
    int pos0 = (b*64 + y)*64 + x;
    int pos1 = 32768 + (b*32 + (y>>1))*32 + (x>>1);
    int pos2 = 40960 + (b*16 + (y>>2))*16 + (x>>2);

    float pA, pB, pC; int zA, zB, zC;
    merge4(pos0, 0, 43008, pA, zA);
    merge4(pos1, 0, 43008, pB, zB);
    merge4(pos2, 0, 43008, pC, zC);
    int z1 = zA; float best = pA;
    if (pB > best) { best = pB; z1 = zB; }
    if (pC > best) { best = pC; z1 = zC; }
    int z2 = merge4max(pos0, 172032, 32768);

    if (cz == 0) {
        out[OFF_Z + ((size_t)(b*2+0)*64 + y)*64 + x] = (float)z1;
        out[OFF_Z + ((size_t)(b*2+1)*64 + y)*64 + x] = (float)z2;
    }

    const float4* r0 = (const float4*)(cb0 + (size_t)z1*CDIM);
    const float4* r1 = (const float4*)(cb1 + (size_t)z2*CDIM);
    size_t obase = (size_t)OFF_STE + (size_t)b*256*4096 + (size_t)y*64 + x;
    for (int c4 = cz*16; c4 < cz*16 + 16; c4++) {
        float4 a = r0[c4], qv = r1[c4];
        int c = c4*4;
        out[obase + (size_t)(c+0)*4096] = 0.5f*(a.x + qv.x);
        out[obase + (size_t)(c+1)*4096] = 0.5f*(a.y + qv.y);
        out[obase + (size_t)(c+2)*4096] = 0.5f*(a.z + qv.z);
        out[obase + (size_t)(c+3)*4096] = 0.5f*(a.w + qv.w);
    }
}

// ======================= launch =======================
extern "C" void kernel_launch(void* const* d_in, const int* in_sizes, int n_in,
                              void* d_out, int out_size)
{
    const float* image     = (const float*)d_in[0];  // (8,3,256,256)
    const float* conv_w    = (const float*)d_in[1];  // (256,3,4,4)
    const float* conv_b    = (const float*)d_in[2];  // (256,)
    const float* codebooks = (const float*)d_in[3];  // (4,512,256)
    float* out = (float*)d_out;

    cudaFuncSetAttribute(dist_mma_kernel, cudaFuncAttributeMaxDynamicSharedMemorySize, DSMEM);

    cbprep_kernel<<<1024, 256>>>(codebooks);

    conv_kernel<<<dim3(128, 8), 256>>>(image, conv_w, conv_b, out, 0);
    conv_kernel<<<dim3(32, 8), 256>>>(image, conv_w, conv_b, out, 1);
    conv_kernel<<<dim3(16, 8), 256>>>(image, conv_w, conv_b, out, 2);

    // cb0: 336 mtiles x 4 quarters = 1344 ; cb1: 256 x 4 = 1024
    dist_mma_kernel<<<2368, 256, DSMEM>>>();

    fuse_kernel<<<dim3(16, 8, 4), 256>>>(codebooks, out);
}

// round 17
// speedup vs baseline: 1.0559x; 1.0559x over previous
#include <cuda_runtime.h>
#include <cuda_fp16.h>
#include <cstdint>

#define CDIM 256
#define KCB  512

static const int N_ENC0  = 8*256*64*64;        // 8388608
static const int OFF_Z   = N_ENC0;
static const int OFF_STE = N_ENC0 + 8*2*64*64; // + 65536

// ---- scratch (device globals; no allocation anywhere) ----
__device__ float g_cbsq[2*KCB];         // ||cb||^2, 1024 rows
// fp16 hi/lo split operands, k-PERMUTED within each 16-chunk:
// j=k&15 -> slot = ((j&7)>>1)*4 + ((j>>3)<<1) + (j&1)   (lane t4 owns slots 4t4..4t4+3)
__device__ __half g_ehi[43008*256];     // concat enc0|enc1|enc2 rows
__device__ __half g_elo[43008*256];
__device__ __half g_cbhi[1024*256];     // cb0 rows 0..511, cb1 rows 512..1023
__device__ __half g_cblo[1024*256];
// per-(quarter, position) partials: cb0: q*43008 + pos ; cb1: 172032 + q*32768 + pos
__device__ float g_hM[303104];
__device__ float g_hL[303104];          // only cb0 slots used
__device__ int   g_hI[303104];

// m16n8k16 fp16 MMA, fp32 accum (sm_80+ PTX)
__device__ __forceinline__ void mma_f16(float* c, uint2 a01, uint2 a23, uint2 b) {
    asm volatile("mma.sync.aligned.m16n8k16.row.col.f32.f16.f16.f32 "
        "{%0,%1,%2,%3}, {%4,%5,%6,%7}, {%8,%9}, {%0,%1,%2,%3};"
        : "+f"(c[0]), "+f"(c[1]), "+f"(c[2]), "+f"(c[3])
        : "r"(a01.x), "r"(a23.x), "r"(a01.y), "r"(a23.y),
          "r"(b.x),  "r"(b.y));
}

__device__ __forceinline__ float ex2a(float x) {
    float r; asm("ex2.approx.f32 %0, %1;" : "=f"(r) : "f"(x)); return r;
}
#define LOG2E 1.4426950408889634f

__device__ __forceinline__ int permcol(int k) {
    int j = k & 15;
    return (k & ~15) + ((j & 7) >> 1)*4 + ((j >> 3) << 1) + (j & 1);
}

// ======================= merged prep kernel =======================
// One launch, 2432 blocks of 256 threads:
//   [0,1024)      conv0: idx -> b=idx&7, bx=idx>>3 (y=bx>>1, xh=bx&1)
//   [1024,1280)   conv1 (inline f=2 avg): idx-1024 -> b=&7, y=>>3
//   [1280,1408)   conv2 (inline f=4 avg): idx-1280 -> b=&7, y=>>3
//   [1408,2432)   cbprep: row = idx-1408
__global__ void __launch_bounds__(256) prep_kernel(
    const float* __restrict__ image, const float* __restrict__ w,
    const float* __restrict__ bias, const float* __restrict__ cbs,
    float* __restrict__ out)
{
    __shared__ __align__(16) float ins[12][256];
    __shared__ float stage[256][17];
    int o = threadIdx.x;
    int blk = blockIdx.x;

    // ---------- cbprep ----------
    if (blk >= 1408) {
        int r = blk - 1408, k = o;
        float v = cbs[(size_t)r*256 + k];
        __half h = __float2half_rn(v);
        __half l = __float2half_rn(v - __half2float(h));
        size_t oo = (size_t)r*256 + permcol(k);
        g_cbhi[oo] = h; g_cblo[oo] = l;
        float s = v*v;
        #pragma unroll
        for (int off = 16; off > 0; off >>= 1) s += __shfl_xor_sync(0xffffffffu, s, off);
        if ((k & 31) == 0) stage[0][k >> 5] = s;
        __syncthreads();
        if (k == 0) {
            float t = 0.f;
            #pragma unroll
            for (int i = 0; i < 8; i++) t += stage[0][i];
            g_cbsq[r] = t;
        }
        return;
    }

    // ---------- conv (3 scales) ----------
    int which, b, y, xh = 0;
    if (blk < 1024)      { which = 0; b = blk & 7; int bx = blk >> 3; y = bx >> 1; xh = bx & 1; }
    else if (blk < 1280) { which = 1; int i = blk - 1024; b = i & 7; y = i >> 3; }
    else                 { which = 2; int i = blk - 1280; b = i & 7; y = i >> 3; }

    if (which == 0) {
        for (int i = o; i < 12*128; i += 256) {
            int x = (i & 127) + 128*xh; int r = i >> 7;
            ins[r][x] = image[(((size_t)b*3 + (r>>2))*256 + 4*y + (r&3))*256 + x];
        }
    } else if (which == 1) {
        for (int i = o; i < 12*128; i += 256) {
            int x = i & 127; int r = i >> 7;
            int ry = 2*(4*y + (r & 3));
            const float* p = image + ((size_t)b*3 + (r>>2))*65536 + ry*256 + 2*x;
            ins[r][x] = 0.25f*(p[0] + p[1] + p[256] + p[257]);
        }
    } else {
        for (int i = o; i < 12*64; i += 256) {
            int x = i & 63; int r = i >> 6;
            int ry = 4*(4*y + (r & 3)) + 1;
            const float* p = image + ((size_t)b*3 + (r>>2))*65536 + ry*256 + 4*x + 1;
            ins[r][x] = 0.25f*(p[0] + p[1] + p[256] + p[257]);
        }
    }

    float wreg[48];
    #pragma unroll
    for (int j = 0; j < 48; j++) wreg[j] = w[(size_t)o*48 + j];
    float bo = bias[o];
    __syncthreads();

    int rowbase = (which == 0) ? (b*64 + y)*64
                : (which == 1) ? 32768 + (b*32 + y)*32
                               : 40960 + (b*16 + y)*16;
    int oc = permcol(o);

    if (which == 0) {
        for (int xc = 32*xh; xc < 32*xh + 32; xc += 16) {
            for (int x2 = 0; x2 < 16; x2 += 2) {
                int x = xc + x2;
                float aA = bo, aB = bo;
                #pragma unroll
                for (int r = 0; r < 12; r++) {
                    float4 vA = *(const float4*)&ins[r][4*x];
                    float4 vB = *(const float4*)&ins[r][4*x + 4];
                    aA += wreg[r*4+0]*vA.x; aB += wreg[r*4+0]*vB.x;
                    aA += wreg[r*4+1]*vA.y; aB += wreg[r*4+1]*vB.y;
                    aA += wreg[r*4+2]*vA.z; aB += wreg[r*4+2]*vB.z;
                    aA += wreg[r*4+3]*vA.w; aB += wreg[r*4+3]*vB.w;
                }
                size_t pA = (size_t)rowbase + x, pB = pA + 1;
                __half hA = __float2half_rn(aA);
                __half lA = __float2half_rn(aA - __half2float(hA));
                __half hB = __float2half_rn(aB);
                __half lB = __float2half_rn(aB - __half2float(hB));
                g_ehi[pA*256 + oc] = hA; g_elo[pA*256 + oc] = lA;
                g_ehi[pB*256 + oc] = hB; g_elo[pB*256 + oc] = lB;
                stage[o][x2] = aA; stage[o][x2+1] = aB;
            }
            __syncthreads();
            int xx = o & 15, cg = o >> 4;
            #pragma unroll
            for (int c0 = 0; c0 < 16; c0++) {
                int c = c0*16 + cg;
                out[((size_t)(b*256 + c)*64 + y)*64 + xc + xx] = stage[c][xx];
            }
            __syncthreads();
        }
    } else {
        int Hout = (which == 1) ? 32 : 16;
        for (int x = 0; x < Hout; x += 2) {
            float aA = bo, aB = bo;
            #pragma unroll
            for (int r = 0; r < 12; r++) {
                float4 vA = *(const float4*)&ins[r][4*x];
                float4 vB = *(const float4*)&ins[r][4*x + 4];
                aA += wreg[r*4+0]*vA.x; aB += wreg[r*4+0]*vB.x;
                aA += wreg[r*4+1]*vA.y; aB += wreg[r*4+1]*vB.y;
                aA += wreg[r*4+2]*vA.z; aB += wreg[r*4+2]*vB.z;
                aA += wreg[r*4+3]*vA.w; aB += wreg[r*4+3]*vB.w;
            }
            size_t pA = (size_t)rowbase + x, pB = pA + 1;
            __half hA = __float2half_rn(aA);
            __half lA = __float2half_rn(aA - __half2float(hA));
            __half hB = __float2half_rn(aB);
            __half lB = __float2half_rn(aB - __half2float(hB));
            g_ehi[pA*256 + oc] = hA; g_elo[pA*256 + oc] = lA;
            g_ehi[pB*256 + oc] = hB; g_elo[pB*256 + oc] = lB;
        }
    }
}

// ======================= fp16 mma.sync distance =======================
// CTA: M=128 positions x N=128 codes (quarter codebook), K=256 in 8 chunks of 32.
// dot ~= Ahi*Bhi + Ahi*Blo + Alo*Bhi (products exact in fp32 accum; dropped lo*lo ~2^-22).
// 8 warps: wm=w&1 (M 64), wn=w>>1 (N 32). Warp tile 64x32, 3 x m16n8k16 per (mt,u).
// Epilogue: two-pass (max/argmax, then sum ex2). cb1 (seg==1) skips L entirely.
#define STRH 48
#define TILEH (128*STRH)
#define DSMEM (4*TILEH*2 + 512)        // 49664 bytes -> 2 CTAs/SM

__global__ void __launch_bounds__(256, 2) dist_mma_kernel()
{
    extern __shared__ char smem[];
    __half* sAhi = (__half*)smem;
    __half* sAlo = sAhi + TILEH;
    __half* sBhi = sAlo + TILEH;
    __half* sBlo = sBhi + TILEH;
    float*  cbs_s = (float*)(smem + 4*TILEH*2);

    int tid = threadIdx.x;
    int lane = tid & 31, w = tid >> 5;
    int g = lane >> 2, t4 = lane & 3;
    int wm = w & 1, wn = w >> 1;

    int blk = blockIdx.x;
    int seg, mtile, q;
    if (blk < 1344) { seg = 0; mtile = blk >> 2; q = blk & 3; }
    else            { seg = 1; mtile = (blk - 1344) >> 2; q = (blk - 1344) & 3; }

    const __half* Ahi_g = g_ehi + (size_t)mtile*128*256;
    const __half* Alo_g = g_elo + (size_t)mtile*128*256;
    int cbrow = (seg ? 512 : 0) + q*128;
    const __half* Bhi_g = g_cbhi + (size_t)cbrow*256;
    const __half* Blo_g = g_cblo + (size_t)cbrow*256;

    if (tid < 128) cbs_s[tid] = g_cbsq[cbrow + tid];

    float acc[4][4][4];
    #pragma unroll
    for (int mt = 0; mt < 4; mt++)
        #pragma unroll
        for (int u = 0; u < 4; u++)
            #pragma unroll
            for (int e = 0; e < 4; e++) acc[mt][u][e] = 0.f;

    const __half* gsrc[4] = {Ahi_g, Alo_g, Bhi_g, Blo_g};
    __half* sdst[4] = {sAhi, sAlo, sBhi, sBlo};

    for (int kc = 0; kc < 8; kc++) {
        if (kc > 0) __syncthreads();
        #pragma unroll
        for (int op = 0; op < 4; op++) {
            #pragma unroll
            for (int it = 0; it < 2; it++) {
                int c = it*256 + tid;
                int r = c >> 2, sgs = c & 3;
                *(uint4*)(sdst[op] + r*STRH + sgs*8) =
                    *(const uint4*)(gsrc[op] + (size_t)r*256 + kc*32 + sgs*8);
            }
        }
        __syncthreads();

        #pragma unroll
        for (int s = 0; s < 2; s++) {
            int ko = s*16 + t4*4;
            uint2 bhf[4], blf[4];
            #pragma unroll
            for (int u = 0; u < 4; u++) {
                int br = (wn*32 + u*8 + g)*STRH + ko;
                bhf[u] = *(uint2*)(sBhi + br);
                blf[u] = *(uint2*)(sBlo + br);
            }
            #pragma unroll
            for (int mt = 0; mt < 4; mt++) {
                int ar = (wm*64 + mt*16 + g)*STRH + ko;
                uint2 ah0 = *(uint2*)(sAhi + ar);
                uint2 ah1 = *(uint2*)(sAhi + ar + 8*STRH);
                uint2 al0 = *(uint2*)(sAlo + ar);
                uint2 al1 = *(uint2*)(sAlo + ar + 8*STRH);
                #pragma unroll
                for (int u = 0; u < 4; u++) {
                    mma_f16(acc[mt][u], ah0, ah1, bhf[u]);
                    mma_f16(acc[mt][u], ah0, ah1, blf[u]);
                    mma_f16(acc[mt][u], al0, al1, bhf[u]);
                }
            }
        }
    }
    __syncthreads();

    float* Mp = (float*)smem;           // [128][4]
    float* Lp = Mp + 512;
    int*   Ip = (int*)(Mp + 1024);

    const float NEG = -3.402823466e38f;
    #pragma unroll
    for (int mt = 0; mt < 4; mt++) {
        #pragma unroll
        for (int half = 0; half < 2; half++) {
            int row = wm*64 + mt*16 + g + half*8;
            float sv[8];
            #pragma unroll
            for (int u = 0; u < 4; u++)
                #pragma unroll
                for (int j = 0; j < 2; j++) {
                    int col = wn*32 + u*8 + 2*t4 + j;
                    sv[u*2 + j] = 2.f*acc[mt][u][half*2 + j] - cbs_s[col];
                }
            float M = NEG; int I = 0;
            #pragma unroll
            for (int t = 0; t < 8; t++) {
                int col = wn*32 + (t >> 1)*8 + 2*t4 + (t & 1);
                if (sv[t] > M) { M = sv[t]; I = col; }
            }
            #pragma unroll
            for (int off = 1; off <= 2; off <<= 1) {
                float m2 = __shfl_xor_sync(0xffffffffu, M, off);
                int   i2 = __shfl_xor_sync(0xffffffffu, I, off);
                if (m2 > M || (m2 == M && i2 < I)) I = i2;
                M = fmaxf(M, m2);
            }
            float L = 0.f;
            if (seg == 0) {
                float ls = 0.f;
                #pragma unroll
                for (int t = 0; t < 8; t++) ls += ex2a((sv[t] - M)*LOG2E);
                #pragma unroll
                for (int off = 1; off <= 2; off <<= 1)
                    ls += __shfl_xor_sync(0xffffffffu, ls, off);
                L = ls;
            }
            if (t4 == 0) { Mp[row*4 + wn] = M; Lp[row*4 + wn] = L; Ip[row*4 + wn] = I; }
        }
    }
    __syncthreads();

    if (tid < 128) {
        float M = Mp[tid*4], L = Lp[tid*4]; int I = Ip[tid*4];
        #pragma unroll
        for (int n = 1; n < 4; n++) {
            float m2 = Mp[tid*4 + n];
            float mn = fmaxf(M, m2);
            L = L*ex2a((M - mn)*LOG2E) + Lp[tid*4 + n]*ex2a((m2 - mn)*LOG2E);
            if (m2 > M) I = Ip[tid*4 + n];
            M = mn;
        }
        int pos = mtile*128 + tid;
        int slot = seg ? (172032 + q*32768 + pos) : (q*43008 + pos);
        g_hM[slot] = M; g_hI[slot] = q*128 + I;
        if (seg == 0) g_hL[slot] = L;
    }
}

// ======================= fuse =======================
__device__ __forceinline__ void merge4(int pos, int base, int stride, float& P, int& idx)
{
    float M = g_hM[base + pos], L = g_hL[base + pos]; int I = g_hI[base + pos];
    #pragma unroll
    for (int n = 1; n < 4; n++) {
        int s = base + n*stride + pos;
        float m2 = g_hM[s], l2 = g_hL[s];
        float mn = fmaxf(M, m2);
        L = L*ex2a((M - mn)*LOG2E) + l2*ex2a((m2 - mn)*LOG2E);
        if (m2 > M) I = g_hI[s];
        M = mn;
    }
    P = 1.f / L; idx = I;
}

__device__ __forceinline__ int merge4max(int pos, int base, int stride)
{
    float M = g_hM[base + pos]; int I = g_hI[base + pos];
    #pragma unroll
    for (int n = 1; n < 4; n++) {
        int s = base + n*stride + pos;
        float m2 = g_hM[s];
        if (m2 > M) { M = m2; I = g_hI[s]; }
    }
    return I;
}

// grid (16, 8, 4): blockIdx.z selects a 64-channel slice; z-writes on slice 0 only.
__global__ void __launch_bounds__(256) fuse_kernel(
    const float* __restrict__ cbs, float* __restrict__ out)
{
    const float* cb0 = cbs;
    const float* cb1 = cbs + (size_t)KCB*CDIM;
    int x = threadIdx.x & 63;
    int y = blockIdx.x*4 + (threadIdx.x >> 6);
    int b = blockIdx.y;
    int cz = blockIdx.z;
    int pos0 = (b*64 + y)*64 + x;
    int pos1 = 32768 + (b*32 + (y>>1))*32 + (x>>1);
    int pos2 = 40960 + (b*16 + (y>>2))*16 + (x>>2);

    float pA, pB, pC; int zA, zB, zC;
    merge4(pos0, 0, 43008, pA, zA);
    merge4(pos1, 0, 43008, pB, zB);
    merge4(pos2, 0, 43008, pC, zC);
    int z1 = zA; float best = pA;
    if (pB > best) { best = pB; z1 = zB; }
    if (pC > best) { best = pC; z1 = zC; }
    int z2 = merge4max(pos0, 172032, 32768);

    if (cz == 0) {
        out[OFF_Z + ((size_t)(b*2+0)*64 + y)*64 + x] = (float)z1;
        out[OFF_Z + ((size_t)(b*2+1)*64 + y)*64 + x] = (float)z2;
    }

    const float4* r0 = (const float4*)(cb0 + (size_t)z1*CDIM);
    const float4* r1 = (const float4*)(cb1 + (size_t)z2*CDIM);
    size_t obase = (size_t)OFF_STE + (size_t)b*256*4096 + (size_t)y*64 + x;
    for (int c4 = cz*16; c4 < cz*16 + 16; c4++) {
        float4 a = r0[c4], qv = r1[c4];
        int c = c4*4;
        out[obase + (size_t)(c+0)*4096] = 0.5f*(a.x + qv.x);
        out[obase + (size_t)(c+1)*4096] = 0.5f*(a.y + qv.y);
        out[obase + (size_t)(c+2)*4096] = 0.5f*(a.z + qv.z);
        out[obase + (size_t)(c+3)*4096] = 0.5f*(a.w + qv.w);
    }
}

// ======================= launch =======================
extern "C" void kernel_launch(void* const* d_in, const int* in_sizes, int n_in,
                              void* d_out, int out_size)
{
    const float* image     = (const float*)d_in[0];  // (8,3,256,256)
    const float* conv_w    = (const float*)d_in[1];  // (256,3,4,4)
    const float* conv_b    = (const float*)d_in[2];  // (256,)
    const float* codebooks = (const float*)d_in[3];  // (4,512,256)
    float* out = (float*)d_out;

    cudaFuncSetAttribute(dist_mma_kernel, cudaFuncAttributeMaxDynamicSharedMemorySize, DSMEM);

    // one merged prep launch: conv0 | conv1 | conv2 | cbprep
    prep_kernel<<<2432, 256>>>(image, conv_w, conv_b, codebooks, out);

    // cb0: 336 mtiles x 4 quarters = 1344 ; cb1: 256 x 4 = 1024
    dist_mma_kernel<<<2368, 256, DSMEM>>>();

    fuse_kernel<<<dim3(16, 8, 4), 256>>>(codebooks, out);
}